// round 16
// baseline (speedup 1.0000x reference)
#include <cuda_runtime.h>
#include <cstdint>
#include <math.h>

#define NB 4
#define NN 512
#define NC 128

// logit scratch (4 MB). Diagonal entries never written; softmax masks them exactly.
__device__ float g_logits[NB * NN * NN];

#define WBUF_WORDS 6912        // 192*36 words per weight ring slot
#define WBUF_BYTES 27648

__device__ __forceinline__ float lrelu(float v) { return v > 0.f ? v : 0.01f * v; }
__device__ __forceinline__ uint32_t smem_u32(const void* p) {
    uint32_t a;
    asm("{ .reg .u64 t; cvta.to.shared.u64 t, %1; cvt.u32.u64 %0, t; }" : "=r"(a) : "l"(p));
    return a;
}

// D(16x8,f32) += A(16x8,tf32,row) * B(8x8,tf32,col)
__device__ __forceinline__ void mma8(float* d, uint32_t a0, uint32_t a1, uint32_t a2, uint32_t a3,
                                     uint32_t b0, uint32_t b1) {
    asm volatile("mma.sync.aligned.m16n8k8.row.col.f32.tf32.tf32.f32 "
                 "{%0,%1,%2,%3},{%4,%5,%6,%7},{%8,%9},{%0,%1,%2,%3};"
                 : "+f"(d[0]), "+f"(d[1]), "+f"(d[2]), "+f"(d[3])
                 : "r"(a0), "r"(a1), "r"(a2), "r"(a3), "r"(b0), "r"(b1));
}

__device__ __forceinline__ int perm32(int kk) { return (kk & 3) * 8 + (kk >> 2); }

#define CP_ASYNC4(dst_u32, src_ptr) \
    asm volatile("cp.async.ca.shared.global [%0], [%1], 4;" :: "r"(dst_u32), "l"(src_ptr) : "memory")
#define CP_COMMIT() asm volatile("cp.async.commit_group;" ::: "memory")
#define CP_WAIT0()  asm volatile("cp.async.wait_group 0;" ::: "memory")

// Stage one 32-k chunk of W[N][K] (src = &W[0][k0], row stride K) into SMEM
// (stride 36 words, permuted) via cp.async. 512 threads.
__device__ __forceinline__ void stage_chunk32(const float* __restrict__ src, int N, int K,
                                              uint32_t dstb, int tid) {
    int PW = N >> 4;
    for (int p = 0; p < PW; ++p) {
        int idx = tid + (p << 9);
        int n = idx >> 5, kk = idx & 31;
        CP_ASYNC4(dstb + (uint32_t)((n * 36 + perm32(kk)) * 4), src + n * K + kk);
    }
    CP_COMMIT();
}

// Compute prologue chunk cc (cols 32cc..32cc+31) of A: buf[r][k]=|xi[k]-xj[k]| (raw fp32 bits).
__device__ __forceinline__ void prologue_chunk(uint32_t* __restrict__ buf, int SA, int cc,
                                               const float* const* __restrict__ rowJ,
                                               const float* const* __restrict__ rowXi, int tid) {
    for (int idx = tid; idx < 128 * 8; idx += 512) {
        int r = idx >> 3, kq8 = idx & 7;
        int kq = cc * 8 + kq8;
        float4 xj4 = *(const float4*)(rowJ[r] + 4 * kq);
        float4 xi4 = *(const float4*)(rowXi[r] + 4 * kq);
        uint32_t* dst = buf + r * SA + cc * 32 + kq8;
        dst[0]  = __float_as_uint(fabsf(xi4.x - xj4.x));
        dst[8]  = __float_as_uint(fabsf(xi4.y - xj4.y));
        dst[16] = __float_as_uint(fabsf(xi4.z - xj4.z));
        dst[24] = __float_as_uint(fabsf(xi4.w - xj4.w));
    }
}

// One MLP layer, in-place on `buf` (fp32-bit words; strides SA->SO, permuted k layout).
// 4-slot weight ring: chunk c lives in slot (BASE+c)&3; one wait+barrier per chunk pair.
// PRO=true (layer 1): A chunks 2,3 are computed during MMA chunks 0,1.
// LAST=true: fuse layer-5 (96->1) into the epilogue via srow atomics.
// 16 warps: warp_m = wid&3 (32 rows), warp_n = wid>>2 (N/4 cols).
template <int N, int K, int SA, int SO, int NEXTN, int NEXTK, int BASE, bool PRO, bool LAST>
__device__ void layer(uint32_t* __restrict__ buf,
                      const float* __restrict__ Wg, const float* __restrict__ bias,
                      const float* __restrict__ nextWg,
                      uint32_t* __restrict__ sW0, uint32_t sw0_bytes,
                      const float* __restrict__ sW5, float* __restrict__ srow,
                      const float* const* __restrict__ rowJ,
                      const float* const* __restrict__ rowXi, int tid)
{
    constexpr int NT  = N / 32;     // 8-wide n-tiles per warp
    constexpr int NCH = K / 32;     // 4, 6, 6, 3

    const int wid = tid >> 5, lane = tid & 31;
    const int g = lane >> 2, t = lane & 3;
    const int mb  = (wid & 3) * 32;
    const int nwb = (wid >> 2) * (N / 4);

    // entry: wait for chunks 0,1 (committed by prev layer / prologue) + order A writes
    CP_WAIT0();
    __syncthreads();

    float d[2][NT][4];
#pragma unroll
    for (int mt = 0; mt < 2; ++mt)
#pragma unroll
        for (int nt = 0; nt < NT; ++nt)
#pragma unroll
            for (int q = 0; q < 4; ++q) d[mt][nt][q] = 0.f;

    for (int c = 0; c < NCH; ++c) {
        if ((c & 1) == 0) {
            // stage two chunks ahead (slots free since the pair-(c/2-1) barrier)
            if (c + 2 < NCH)
                stage_chunk32(Wg + (c + 2) * 32, N, K,
                              sw0_bytes + (uint32_t)(((BASE + c + 2) & 3) * WBUF_BYTES), tid);
            else if (NEXTN > 0)
                stage_chunk32(nextWg, NEXTN, NEXTK,
                              sw0_bytes + (uint32_t)(((BASE + NCH) & 3) * WBUF_BYTES), tid);
            if (c + 3 < NCH)
                stage_chunk32(Wg + (c + 3) * 32, N, K,
                              sw0_bytes + (uint32_t)(((BASE + c + 3) & 3) * WBUF_BYTES), tid);
            else if (NEXTN > 0 && c + 2 >= NCH)
                stage_chunk32(nextWg + 32, NEXTN, NEXTK,
                              sw0_bytes + (uint32_t)(((BASE + NCH + 1) & 3) * WBUF_BYTES), tid);
        }
        // pipelined A prologue (layer 1 only): chunk c+2 during MMA chunk c (c=0,1)
        if (PRO && c < 2)
            prologue_chunk(buf, SA, c + 2, rowJ, rowXi, tid);

        const uint32_t* sWc = sW0 + ((BASE + c) & 3) * WBUF_WORDS;
#pragma unroll
        for (int h = 0; h < 2; ++h) {
            uint32_t bf[NT][4];
#pragma unroll
            for (int nt = 0; nt < NT; ++nt) {
                int n = nwb + nt * 8 + g;
                *(uint4*)bf[nt] = *(const uint4*)(sWc + n * 36 + t * 8 + 4 * h);
            }
            uint32_t av[2][2][4];
#pragma unroll
            for (int mt = 0; mt < 2; ++mt) {
                int r0 = mb + mt * 16 + g;
                *(uint4*)av[mt][0] = *(const uint4*)(buf + r0 * SA + c * 32 + t * 8 + 4 * h);
                *(uint4*)av[mt][1] = *(const uint4*)(buf + (r0 + 8) * SA + c * 32 + t * 8 + 4 * h);
            }
#pragma unroll
            for (int ks = 0; ks < 2; ++ks)
#pragma unroll
                for (int mt = 0; mt < 2; ++mt)
#pragma unroll
                    for (int nt = 0; nt < NT; ++nt)
                        mma8(d[mt][nt],
                             av[mt][0][2 * ks], av[mt][1][2 * ks],
                             av[mt][0][2 * ks + 1], av[mt][1][2 * ks + 1],
                             bf[nt][2 * ks], bf[nt][2 * ks + 1]);
        }
        if ((c & 1) == 1 || c == NCH - 1) { CP_WAIT0(); __syncthreads(); }
    }

    if (!LAST) {
        // epilogue: bias + lrelu, raw fp32 bits, in place, permuted columns
#pragma unroll
        for (int mt = 0; mt < 2; ++mt) {
            int r0 = mb + mt * 16 + g;
#pragma unroll
            for (int nt = 0; nt < NT; ++nt) {
                int cb = nwb + nt * 8 + 2 * t;
                float bb0 = bias[cb], bb1 = bias[cb + 1];
                int w0 = (cb >> 5) * 32 + perm32(cb & 31);
                int w1 = ((cb + 1) >> 5) * 32 + perm32((cb + 1) & 31);
                buf[r0 * SO + w0]       = __float_as_uint(lrelu(d[mt][nt][0] + bb0));
                buf[r0 * SO + w1]       = __float_as_uint(lrelu(d[mt][nt][1] + bb1));
                buf[(r0 + 8) * SO + w0] = __float_as_uint(lrelu(d[mt][nt][2] + bb0));
                buf[(r0 + 8) * SO + w1] = __float_as_uint(lrelu(d[mt][nt][3] + bb1));
            }
        }
    } else {
        // fused L4-epilogue + L5: v = lrelu(d+bias); partial dot with w5; reduce; atomicAdd
        float pr[2][2] = {{0.f, 0.f}, {0.f, 0.f}};   // [mt][row-half]
#pragma unroll
        for (int mt = 0; mt < 2; ++mt)
#pragma unroll
            for (int nt = 0; nt < NT; ++nt) {
                int cb = nwb + nt * 8 + 2 * t;
                float bb0 = bias[cb], bb1 = bias[cb + 1];
                float w50 = sW5[cb], w51 = sW5[cb + 1];
                pr[mt][0] = fmaf(lrelu(d[mt][nt][0] + bb0), w50, pr[mt][0]);
                pr[mt][0] = fmaf(lrelu(d[mt][nt][1] + bb1), w51, pr[mt][0]);
                pr[mt][1] = fmaf(lrelu(d[mt][nt][2] + bb0), w50, pr[mt][1]);
                pr[mt][1] = fmaf(lrelu(d[mt][nt][3] + bb1), w51, pr[mt][1]);
            }
#pragma unroll
        for (int mt = 0; mt < 2; ++mt)
#pragma unroll
            for (int hh = 0; hh < 2; ++hh) {
                pr[mt][hh] += __shfl_xor_sync(0xffffffffu, pr[mt][hh], 1);
                pr[mt][hh] += __shfl_xor_sync(0xffffffffu, pr[mt][hh], 2);
            }
        if (t == 0) {
#pragma unroll
            for (int mt = 0; mt < 2; ++mt) {
                atomicAdd(&srow[mb + mt * 16 + g],     pr[mt][0]);
                atomicAdd(&srow[mb + mt * 16 + 8 + g], pr[mt][1]);
            }
        }
    }
    // next layer's entry wait+sync orders the epilogue writes
}

extern __shared__ uint32_t dynsm[];

__global__ void __launch_bounds__(512, 1)
mlp_kernel(const float* __restrict__ x,
           const float* __restrict__ w1, const float* __restrict__ b1,
           const float* __restrict__ w2, const float* __restrict__ b2,
           const float* __restrict__ w3, const float* __restrict__ b3,
           const float* __restrict__ w4, const float* __restrict__ b4,
           const float* __restrict__ w5, const float* __restrict__ b5)
{
    __shared__ float sXi[256];     // [0:128) = x[I0], [128:256) = x[I1]
    __shared__ float sBias[576];
    __shared__ float sW5[96];
    __shared__ float sB5;
    __shared__ float srow[128];
    __shared__ const float* sRowJ[128];
    __shared__ const float* sRowXi[128];

    const int tid = threadIdx.x;

    // ---- exact-dedup tile decode: 1024 CTAs per batch (proven in R10/R13/R14/R15) ----
    const int blk = blockIdx.x;
    const int b = blk >> 10;
    const int t = blk & 1023;
    int I0, I1, rsplit, jbase, pp = 0;
    bool isDiag = false;
    if (t < 384)      { I0 = t / 3;              jbase = 128 * (1 + t % 3); }
    else if (t < 640) { int l = t - 384; I0 = 128 + (l >> 1); jbase = 128 * (2 + (l & 1)); }
    else if (t < 768) { I0 = 256 + (t - 640);    jbase = 384; }
    else {
        isDiag = true;
        int dd = t - 768;
        int ibd = dd >> 6;
        pp = dd & 63;
        jbase = ibd * 128;
        I0 = jbase + pp;
        I1 = jbase + 127 - pp;
    }
    if (!isDiag) { I1 = I0; rsplit = 128; }
    else rsplit = 127 - pp;

    const float* xb = x + (size_t)b * NN * NC;

    uint32_t* buf = dynsm;                 // 128*196 words, in-place across layers
    uint32_t* sW0 = buf + 128 * 196;       // 4-slot weight ring, 6912 words each
    const uint32_t sw0_bytes = smem_u32(sW0);

    if (tid < 128) {
        sXi[tid] = xb[(size_t)I0 * NC + tid];
        srow[tid] = 0.f;
        // per-row source pointers for the (pipelined) prologue
        int r = tid;
        int J;
        if (isDiag) J = (r == 127) ? jbase : (jbase + 1 + r + ((r < rsplit) ? pp : 0));
        else        J = jbase + r;
        sRowJ[r]  = xb + (size_t)J * NC;
        sRowXi[r] = sXi + ((r < rsplit) ? 0 : 128);
    } else if (tid < 256) {
        sXi[tid] = xb[(size_t)I1 * NC + (tid - 128)];
    }
    if (tid < 192) { sBias[tid] = b1[tid]; sBias[192 + tid] = b2[tid]; }
    if (tid < 96)  { sBias[384 + tid] = b3[tid]; sBias[480 + tid] = b4[tid]; sW5[tid] = w5[tid]; }
    if (tid == 0)  sB5 = b5[0];

    // stage w1 chunks 0,1 immediately (slots 0,1; overlaps xi staging + prologue)
    stage_chunk32(w1,      192, 128, sw0_bytes,              tid);
    stage_chunk32(w1 + 32, 192, 128, sw0_bytes + WBUF_BYTES, tid);
    __syncthreads();   // sXi / sRowJ / sRowXi ready

    // pre-layer prologue: only A chunks 0,1 (chunks 2,3 pipelined inside layer 1)
    prologue_chunk(buf, 132, 0, sRowJ, sRowXi, tid);
    prologue_chunk(buf, 132, 1, sRowJ, sRowXi, tid);
    // layer entry performs CP_WAIT0 + __syncthreads (orders prologue writes too)

    // ring BASE per layer: 0, (0+4)&3=0, (0+6)&3=2, (2+6)&3=0
    layer<192, 128, 132, 196, 192, 192, 0, true,  false>(buf, w1, sBias + 0,   w2, sW0, sw0_bytes, sW5, srow, sRowJ, sRowXi, tid);
    layer<192, 192, 196, 196,  96, 192, 0, false, false>(buf, w2, sBias + 192, w3, sW0, sw0_bytes, sW5, srow, sRowJ, sRowXi, tid);
    layer< 96, 192, 196, 100,  96,  96, 2, false, false>(buf, w3, sBias + 384, w4, sW0, sw0_bytes, sW5, srow, sRowJ, sRowXi, tid);
    layer< 96,  96, 100, 100,   0,   0, 0, false, true >(buf, w4, sBias + 480, (const float*)0, sW0, sw0_bytes, sW5, srow, sRowJ, sRowXi, tid);
    __syncthreads();   // srow atomics visible

    // write logits (fused L5 already accumulated in srow)
    if (tid < 128 && !(isDiag && tid == 127)) {
        float lg = srow[tid] + sB5;
        int I = (tid < rsplit) ? I0 : I1;
        int J;
        if (isDiag) J = jbase + 1 + tid + ((tid < rsplit) ? pp : 0);
        else        J = jbase + tid;
        g_logits[((size_t)b * NN + I) * NN + J] = lg;   // direct
        g_logits[((size_t)b * NN + J) * NN + I] = lg;   // mirror (d symmetric)
    }
}

__global__ void __launch_bounds__(256)
softmax_kernel(float2* __restrict__ out)
{
    __shared__ float sred[8];
    __shared__ float sval;
    int row = blockIdx.x;
    int i   = row & (NN - 1);
    const float* L = g_logits + (size_t)row * NN;
    int tid  = threadIdx.x;
    int lane = tid & 31, warp = tid >> 5;

    // self-edge masked exactly (diagonal logits are never computed)
    float l0 = (tid == i)       ? -1e8f : L[tid];
    float l1 = (tid + 256 == i) ? -1e8f : L[tid + 256];

    float m = fmaxf(l0, l1);
#pragma unroll
    for (int o = 16; o > 0; o >>= 1) m = fmaxf(m, __shfl_xor_sync(0xffffffffu, m, o));
    if (lane == 0) sred[warp] = m;
    __syncthreads();
    if (tid == 0) {
        float v = sred[0];
        for (int w = 1; w < 8; ++w) v = fmaxf(v, sred[w]);
        sval = v;
    }
    __syncthreads();
    float M  = sval;
    float e0 = expf(l0 - M);
    float e1 = expf(l1 - M);
    float s  = e0 + e1;
#pragma unroll
    for (int o = 16; o > 0; o >>= 1) s += __shfl_xor_sync(0xffffffffu, s, o);
    __syncthreads();
    if (lane == 0) sred[warp] = s;
    __syncthreads();
    if (tid == 0) {
        float v = 0.f;
        for (int w = 0; w < 8; ++w) v += sred[w];
        sval = 1.0f / v;
    }
    __syncthreads();
    float inv = sval;

    float2* o2 = out + (size_t)row * NN;
    o2[tid]       = make_float2(tid == i ? 1.f : 0.f,       e0 * inv);
    o2[tid + 256] = make_float2(tid + 256 == i ? 1.f : 0.f, e1 * inv);
}

extern "C" void kernel_launch(void* const* d_in, const int* in_sizes, int n_in,
                              void* d_out, int out_size)
{
    const float* x  = (const float*)d_in[0];
    // d_in[1] = W_id (exact identity; regenerated analytically)
    const float* w1 = (const float*)d_in[2];
    const float* b1 = (const float*)d_in[3];
    const float* w2 = (const float*)d_in[4];
    const float* b2 = (const float*)d_in[5];
    const float* w3 = (const float*)d_in[6];
    const float* b3 = (const float*)d_in[7];
    const float* w4 = (const float*)d_in[8];
    const float* b4 = (const float*)d_in[9];
    const float* w5 = (const float*)d_in[10];
    const float* b5 = (const float*)d_in[11];
    float2* out = (float2*)d_out;

    // dyn smem: act buf 128x196 + 4-slot weight ring 4x6912 = 52736 words = 210,944 B
    size_t smem_bytes = (128 * 196 + 4 * WBUF_WORDS) * sizeof(uint32_t);
    cudaFuncSetAttribute(mlp_kernel, cudaFuncAttributeMaxDynamicSharedMemorySize,
                         (int)smem_bytes);

    // exact-dedup tile set: 4 batches x 1024 CTAs
    mlp_kernel<<<NB * 1024, 512, smem_bytes>>>(
        x, w1, b1, w2, b2, w3, b3, w4, b4, w5, b5);
    softmax_kernel<<<NB * NN, 256>>>(out);
}

// round 17
// speedup vs baseline: 1.5150x; 1.5150x over previous
#include <cuda_runtime.h>
#include <cstdint>
#include <math.h>

#define NB 4
#define NN 512
#define NC 128

// logit scratch (4 MB). Diagonal entries never written; softmax masks them exactly.
__device__ float g_logits[NB * NN * NN];

#define WBUF_WORDS 6912        // 192*36 words per weight ring slot
#define WBUF_BYTES 27648

__device__ __forceinline__ uint32_t f2tf32(float f) {
    uint32_t r;
    asm("cvt.rna.tf32.f32 %0, %1;" : "=r"(r) : "f"(f));
    return r;
}
__device__ __forceinline__ float lrelu(float v) { return v > 0.f ? v : 0.01f * v; }
__device__ __forceinline__ uint32_t smem_u32(const void* p) {
    uint32_t a;
    asm("{ .reg .u64 t; cvta.to.shared.u64 t, %1; cvt.u32.u64 %0, t; }" : "=r"(a) : "l"(p));
    return a;
}

// D(16x8,f32) += A(16x8,tf32,row) * B(8x8,tf32,col)
__device__ __forceinline__ void mma8(float* d, uint32_t a0, uint32_t a1, uint32_t a2, uint32_t a3,
                                     uint32_t b0, uint32_t b1) {
    asm volatile("mma.sync.aligned.m16n8k8.row.col.f32.tf32.tf32.f32 "
                 "{%0,%1,%2,%3},{%4,%5,%6,%7},{%8,%9},{%0,%1,%2,%3};"
                 : "+f"(d[0]), "+f"(d[1]), "+f"(d[2]), "+f"(d[3])
                 : "r"(a0), "r"(a1), "r"(a2), "r"(a3), "r"(b0), "r"(b1));
}

__device__ __forceinline__ int perm32(int kk) { return (kk & 3) * 8 + (kk >> 2); }

#define CP_ASYNC4(dst_u32, src_ptr) \
    asm volatile("cp.async.ca.shared.global [%0], [%1], 4;" :: "r"(dst_u32), "l"(src_ptr) : "memory")
#define CP_COMMIT() asm volatile("cp.async.commit_group;" ::: "memory")
#define CP_WAIT0()  asm volatile("cp.async.wait_group 0;" ::: "memory")

// Stage one 32-k chunk of W[N][K] (src = &W[0][k0], row stride K) into SMEM
// (stride 36 words, permuted) via cp.async. 512 threads.
__device__ __forceinline__ void stage_chunk32(const float* __restrict__ src, int N, int K,
                                              uint32_t dstb, int tid) {
    int PW = N >> 4;
    for (int p = 0; p < PW; ++p) {
        int idx = tid + (p << 9);
        int n = idx >> 5, kk = idx & 31;
        CP_ASYNC4(dstb + (uint32_t)((n * 36 + perm32(kk)) * 4), src + n * K + kk);
    }
    CP_COMMIT();
}

// Compute prologue chunk cc (cols 32cc..32cc+31) of A: buf[r][k]=tf32(|xi[k]-xj[k]|).
__device__ __forceinline__ void prologue_chunk(uint32_t* __restrict__ buf, int SA, int cc,
                                               const float* const* __restrict__ rowJ,
                                               const float* const* __restrict__ rowXi, int tid) {
    for (int idx = tid; idx < 128 * 8; idx += 512) {
        int r = idx >> 3, kq8 = idx & 7;
        int kq = cc * 8 + kq8;
        float4 xj4 = *(const float4*)(rowJ[r] + 4 * kq);
        float4 xi4 = *(const float4*)(rowXi[r] + 4 * kq);
        uint32_t* dst = buf + r * SA + cc * 32 + kq8;
        dst[0]  = f2tf32(fabsf(xi4.x - xj4.x));
        dst[8]  = f2tf32(fabsf(xi4.y - xj4.y));
        dst[16] = f2tf32(fabsf(xi4.z - xj4.z));
        dst[24] = f2tf32(fabsf(xi4.w - xj4.w));
    }
}

// One MLP layer, in-place on `buf` (tf32 words; strides SA->SO, permuted k layout).
// 4-slot weight ring: chunk c lives in slot (BASE+c)&3; one wait+barrier per chunk pair.
// PRO=true (layer 1): A chunks 2,3 are computed during MMA chunks 0,1 (pair barrier
// at c=1 orders the writes before their first read at c=2,3).
// LAST=true: fuse layer-5 (96->1) into the epilogue via srow atomics.
// 16 warps: warp_m = wid&3 (32 rows), warp_n = wid>>2 (N/4 cols).
template <int N, int K, int SA, int SO, int NEXTN, int NEXTK, int BASE, bool PRO, bool LAST>
__device__ void layer(uint32_t* __restrict__ buf,
                      const float* __restrict__ Wg, const float* __restrict__ bias,
                      const float* __restrict__ nextWg,
                      uint32_t* __restrict__ sW0, uint32_t sw0_bytes,
                      const float* __restrict__ sW5, float* __restrict__ srow,
                      const float* const* __restrict__ rowJ,
                      const float* const* __restrict__ rowXi, int tid)
{
    constexpr int NT  = N / 32;     // 8-wide n-tiles per warp
    constexpr int NCH = K / 32;     // 4, 6, 6, 3

    const int wid = tid >> 5, lane = tid & 31;
    const int g = lane >> 2, t = lane & 3;
    const int mb  = (wid & 3) * 32;
    const int nwb = (wid >> 2) * (N / 4);

    // entry: wait for chunks 0,1 (committed by prev layer / prologue) + order A writes
    CP_WAIT0();
    __syncthreads();

    float d[2][NT][4];
#pragma unroll
    for (int mt = 0; mt < 2; ++mt)
#pragma unroll
        for (int nt = 0; nt < NT; ++nt)
#pragma unroll
            for (int q = 0; q < 4; ++q) d[mt][nt][q] = 0.f;

    for (int c = 0; c < NCH; ++c) {
        if ((c & 1) == 0) {
            // stage two chunks ahead (slots free since the pair-(c/2-1) barrier)
            if (c + 2 < NCH)
                stage_chunk32(Wg + (c + 2) * 32, N, K,
                              sw0_bytes + (uint32_t)(((BASE + c + 2) & 3) * WBUF_BYTES), tid);
            else if (NEXTN > 0)
                stage_chunk32(nextWg, NEXTN, NEXTK,
                              sw0_bytes + (uint32_t)(((BASE + NCH) & 3) * WBUF_BYTES), tid);
            if (c + 3 < NCH)
                stage_chunk32(Wg + (c + 3) * 32, N, K,
                              sw0_bytes + (uint32_t)(((BASE + c + 3) & 3) * WBUF_BYTES), tid);
            else if (NEXTN > 0 && c + 2 >= NCH)
                stage_chunk32(nextWg + 32, NEXTN, NEXTK,
                              sw0_bytes + (uint32_t)(((BASE + NCH + 1) & 3) * WBUF_BYTES), tid);
        }
        // pipelined A prologue (layer 1 only): chunk c+2 during MMA chunk c (c=0,1)
        if (PRO && c < 2)
            prologue_chunk(buf, SA, c + 2, rowJ, rowXi, tid);

        const uint32_t* sWc = sW0 + ((BASE + c) & 3) * WBUF_WORDS;
#pragma unroll
        for (int h = 0; h < 2; ++h) {
            uint32_t bf[NT][4];
#pragma unroll
            for (int nt = 0; nt < NT; ++nt) {
                int n = nwb + nt * 8 + g;
                *(uint4*)bf[nt] = *(const uint4*)(sWc + n * 36 + t * 8 + 4 * h);
            }
            uint32_t av[2][2][4];
#pragma unroll
            for (int mt = 0; mt < 2; ++mt) {
                int r0 = mb + mt * 16 + g;
                *(uint4*)av[mt][0] = *(const uint4*)(buf + r0 * SA + c * 32 + t * 8 + 4 * h);
                *(uint4*)av[mt][1] = *(const uint4*)(buf + (r0 + 8) * SA + c * 32 + t * 8 + 4 * h);
            }
#pragma unroll
            for (int ks = 0; ks < 2; ++ks)
#pragma unroll
                for (int mt = 0; mt < 2; ++mt)
#pragma unroll
                    for (int nt = 0; nt < NT; ++nt)
                        mma8(d[mt][nt],
                             av[mt][0][2 * ks], av[mt][1][2 * ks],
                             av[mt][0][2 * ks + 1], av[mt][1][2 * ks + 1],
                             bf[nt][2 * ks], bf[nt][2 * ks + 1]);
        }
        if ((c & 1) == 1 || c == NCH - 1) { CP_WAIT0(); __syncthreads(); }
    }

    if (!LAST) {
        // epilogue: bias + lrelu + tf32, in place (inputs dead after final barrier), permuted
#pragma unroll
        for (int mt = 0; mt < 2; ++mt) {
            int r0 = mb + mt * 16 + g;
#pragma unroll
            for (int nt = 0; nt < NT; ++nt) {
                int cb = nwb + nt * 8 + 2 * t;
                float bb0 = bias[cb], bb1 = bias[cb + 1];
                int w0 = (cb >> 5) * 32 + perm32(cb & 31);
                int w1 = ((cb + 1) >> 5) * 32 + perm32((cb + 1) & 31);
                buf[r0 * SO + w0]       = f2tf32(lrelu(d[mt][nt][0] + bb0));
                buf[r0 * SO + w1]       = f2tf32(lrelu(d[mt][nt][1] + bb1));
                buf[(r0 + 8) * SO + w0] = f2tf32(lrelu(d[mt][nt][2] + bb0));
                buf[(r0 + 8) * SO + w1] = f2tf32(lrelu(d[mt][nt][3] + bb1));
            }
        }
    } else {
        // fused L4-epilogue + L5: v = lrelu(d+bias); partial dot with w5; reduce; atomicAdd
        float pr[2][2] = {{0.f, 0.f}, {0.f, 0.f}};   // [mt][row-half]
#pragma unroll
        for (int mt = 0; mt < 2; ++mt)
#pragma unroll
            for (int nt = 0; nt < NT; ++nt) {
                int cb = nwb + nt * 8 + 2 * t;
                float bb0 = bias[cb], bb1 = bias[cb + 1];
                float w50 = sW5[cb], w51 = sW5[cb + 1];
                pr[mt][0] = fmaf(lrelu(d[mt][nt][0] + bb0), w50, pr[mt][0]);
                pr[mt][0] = fmaf(lrelu(d[mt][nt][1] + bb1), w51, pr[mt][0]);
                pr[mt][1] = fmaf(lrelu(d[mt][nt][2] + bb0), w50, pr[mt][1]);
                pr[mt][1] = fmaf(lrelu(d[mt][nt][3] + bb1), w51, pr[mt][1]);
            }
#pragma unroll
        for (int mt = 0; mt < 2; ++mt)
#pragma unroll
            for (int hh = 0; hh < 2; ++hh) {
                pr[mt][hh] += __shfl_xor_sync(0xffffffffu, pr[mt][hh], 1);
                pr[mt][hh] += __shfl_xor_sync(0xffffffffu, pr[mt][hh], 2);
            }
        if (t == 0) {
#pragma unroll
            for (int mt = 0; mt < 2; ++mt) {
                atomicAdd(&srow[mb + mt * 16 + g],     pr[mt][0]);
                atomicAdd(&srow[mb + mt * 16 + 8 + g], pr[mt][1]);
            }
        }
    }
    // next layer's entry wait+sync orders the epilogue writes
}

extern __shared__ uint32_t dynsm[];

__global__ void __launch_bounds__(512, 1)
mlp_kernel(const float* __restrict__ x,
           const float* __restrict__ w1, const float* __restrict__ b1,
           const float* __restrict__ w2, const float* __restrict__ b2,
           const float* __restrict__ w3, const float* __restrict__ b3,
           const float* __restrict__ w4, const float* __restrict__ b4,
           const float* __restrict__ w5, const float* __restrict__ b5)
{
    __shared__ float sXi[256];     // [0:128) = x[I0], [128:256) = x[I1]
    __shared__ float sBias[576];
    __shared__ float sW5[96];
    __shared__ float sB5;
    __shared__ float srow[128];
    __shared__ const float* sRowJ[128];
    __shared__ const float* sRowXi[128];

    const int tid = threadIdx.x;

    // ---- exact-dedup tile decode: 1024 CTAs per batch ----
    const int blk = blockIdx.x;
    const int b = blk >> 10;
    const int t = blk & 1023;
    int I0, I1, rsplit, jbase, pp = 0;
    bool isDiag = false;
    if (t < 384)      { I0 = t / 3;              jbase = 128 * (1 + t % 3); }
    else if (t < 640) { int l = t - 384; I0 = 128 + (l >> 1); jbase = 128 * (2 + (l & 1)); }
    else if (t < 768) { I0 = 256 + (t - 640);    jbase = 384; }
    else {
        isDiag = true;
        int dd = t - 768;
        int ibd = dd >> 6;
        pp = dd & 63;
        jbase = ibd * 128;
        I0 = jbase + pp;
        I1 = jbase + 127 - pp;
    }
    if (!isDiag) { I1 = I0; rsplit = 128; }
    else rsplit = 127 - pp;

    const float* xb = x + (size_t)b * NN * NC;

    uint32_t* buf = dynsm;                 // 128*196 words, in-place across layers
    uint32_t* sW0 = buf + 128 * 196;       // 4-slot weight ring, 6912 words each
    const uint32_t sw0_bytes = smem_u32(sW0);

    if (tid < 128) {
        sXi[tid] = xb[(size_t)I0 * NC + tid];
        srow[tid] = 0.f;
        // per-row source pointers for the (pipelined) prologue
        int r = tid;
        int J;
        if (isDiag) J = (r == 127) ? jbase : (jbase + 1 + r + ((r < rsplit) ? pp : 0));
        else        J = jbase + r;
        sRowJ[r]  = xb + (size_t)J * NC;
        sRowXi[r] = sXi + ((r < rsplit) ? 0 : 128);
    } else if (tid < 256) {
        sXi[tid] = xb[(size_t)I1 * NC + (tid - 128)];
    }
    if (tid < 192) { sBias[tid] = b1[tid]; sBias[192 + tid] = b2[tid]; }
    if (tid < 96)  { sBias[384 + tid] = b3[tid]; sBias[480 + tid] = b4[tid]; sW5[tid] = w5[tid]; }
    if (tid == 0)  sB5 = b5[0];

    // stage w1 chunks 0,1 immediately (slots 0,1; overlaps xi staging + prologue)
    stage_chunk32(w1,      192, 128, sw0_bytes,              tid);
    stage_chunk32(w1 + 32, 192, 128, sw0_bytes + WBUF_BYTES, tid);
    __syncthreads();   // sXi / sRowJ / sRowXi ready

    // pre-layer prologue: only A chunks 0,1 (chunks 2,3 pipelined inside layer 1)
    prologue_chunk(buf, 132, 0, sRowJ, sRowXi, tid);
    prologue_chunk(buf, 132, 1, sRowJ, sRowXi, tid);
    // layer entry performs CP_WAIT0 + __syncthreads (orders prologue writes too)

    // ring BASE per layer: 0, (0+4)&3=0, (0+6)&3=2, (2+6)&3=0
    layer<192, 128, 132, 196, 192, 192, 0, true,  false>(buf, w1, sBias + 0,   w2, sW0, sw0_bytes, sW5, srow, sRowJ, sRowXi, tid);
    layer<192, 192, 196, 196,  96, 192, 0, false, false>(buf, w2, sBias + 192, w3, sW0, sw0_bytes, sW5, srow, sRowJ, sRowXi, tid);
    layer< 96, 192, 196, 100,  96,  96, 2, false, false>(buf, w3, sBias + 384, w4, sW0, sw0_bytes, sW5, srow, sRowJ, sRowXi, tid);
    layer< 96,  96, 100, 100,   0,   0, 0, false, true >(buf, w4, sBias + 480, (const float*)0, sW0, sw0_bytes, sW5, srow, sRowJ, sRowXi, tid);
    __syncthreads();   // srow atomics visible

    // write logits (fused L5 already accumulated in srow)
    if (tid < 128 && !(isDiag && tid == 127)) {
        float lg = srow[tid] + sB5;
        int I = (tid < rsplit) ? I0 : I1;
        int J;
        if (isDiag) J = jbase + 1 + tid + ((tid < rsplit) ? pp : 0);
        else        J = jbase + tid;
        g_logits[((size_t)b * NN + I) * NN + J] = lg;   // direct
        g_logits[((size_t)b * NN + J) * NN + I] = lg;   // mirror (d symmetric)
    }
}

__global__ void __launch_bounds__(256)
softmax_kernel(float2* __restrict__ out)
{
    __shared__ float sred[8];
    __shared__ float sval;
    int row = blockIdx.x;
    int i   = row & (NN - 1);
    const float* L = g_logits + (size_t)row * NN;
    int tid  = threadIdx.x;
    int lane = tid & 31, warp = tid >> 5;

    // self-edge masked exactly (diagonal logits are never computed)
    float l0 = (tid == i)       ? -1e8f : L[tid];
    float l1 = (tid + 256 == i) ? -1e8f : L[tid + 256];

    float m = fmaxf(l0, l1);
#pragma unroll
    for (int o = 16; o > 0; o >>= 1) m = fmaxf(m, __shfl_xor_sync(0xffffffffu, m, o));
    if (lane == 0) sred[warp] = m;
    __syncthreads();
    if (tid == 0) {
        float v = sred[0];
        for (int w = 1; w < 8; ++w) v = fmaxf(v, sred[w]);
        sval = v;
    }
    __syncthreads();
    float M  = sval;
    float e0 = expf(l0 - M);
    float e1 = expf(l1 - M);
    float s  = e0 + e1;
#pragma unroll
    for (int o = 16; o > 0; o >>= 1) s += __shfl_xor_sync(0xffffffffu, s, o);
    __syncthreads();
    if (lane == 0) sred[warp] = s;
    __syncthreads();
    if (tid == 0) {
        float v = 0.f;
        for (int w = 0; w < 8; ++w) v += sred[w];
        sval = 1.0f / v;
    }
    __syncthreads();
    float inv = sval;

    float2* o2 = out + (size_t)row * NN;
    o2[tid]       = make_float2(tid == i ? 1.f : 0.f,       e0 * inv);
    o2[tid + 256] = make_float2(tid + 256 == i ? 1.f : 0.f, e1 * inv);
}

extern "C" void kernel_launch(void* const* d_in, const int* in_sizes, int n_in,
                              void* d_out, int out_size)
{
    const float* x  = (const float*)d_in[0];
    // d_in[1] = W_id (exact identity; regenerated analytically)
    const float* w1 = (const float*)d_in[2];
    const float* b1 = (const float*)d_in[3];
    const float* w2 = (const float*)d_in[4];
    const float* b2 = (const float*)d_in[5];
    const float* w3 = (const float*)d_in[6];
    const float* b3 = (const float*)d_in[7];
    const float* w4 = (const float*)d_in[8];
    const float* b4 = (const float*)d_in[9];
    const float* w5 = (const float*)d_in[10];
    const float* b5 = (const float*)d_in[11];
    float2* out = (float2*)d_out;

    // dyn smem: act buf 128x196 + 4-slot weight ring 4x6912 = 52736 words = 210,944 B
    size_t smem_bytes = (128 * 196 + 4 * WBUF_WORDS) * sizeof(uint32_t);
    cudaFuncSetAttribute(mlp_kernel, cudaFuncAttributeMaxDynamicSharedMemorySize,
                         (int)smem_bytes);

    // exact-dedup tile set: 4 batches x 1024 CTAs
    mlp_kernel<<<NB * 1024, 512, smem_bytes>>>(
        x, w1, b1, w2, b2, w3, b3, w4, b4, w5, b5);
    softmax_kernel<<<NB * NN, 256>>>(out);
}